// round 2
// baseline (speedup 1.0000x reference)
#include <cuda_runtime.h>
#include <math.h>

// Problem constants (fixed by the reference)
#define BGRAPH   512
#define NPG      256                 // nodes per graph (== max_nodes)
#define NROWS    (BGRAPH * NPG)      // 131072
#define INDIM    128
#define HIDN     128
#define D2       256                 // 2*HID
#define MT       64                  // rows per CTA tile (64 | 256 -> tile within one graph)
#define KT       64                  // K chunk staged in smem
#define NTHREADS 256

// smem layout (floats): A[MT*D2] | A2[MT*D2] | Wt[KT*D2] | sb1[D2] | sb2[D2] | sW3[2*D2] | sEmb[HIDN]
#define SM_FLOATS (3 * MT * D2 + 2 * D2 + 2 * D2 + HIDN)
#define SM_BYTES  (SM_FLOATS * 4)

__device__ __forceinline__ void do_layer(const float* __restrict__ Ain,
                                         const float* __restrict__ Wg,
                                         float* __restrict__ Wt,
                                         const float* __restrict__ sbias,
                                         int tid, int tx, int ty,
                                         float (&acc)[8][8])
{
    #pragma unroll
    for (int m = 0; m < 8; m++)
        #pragma unroll
        for (int j = 0; j < 8; j++)
            acc[m][j] = sbias[tx * 8 + j];

    #pragma unroll 1
    for (int kc = 0; kc < D2 / KT; kc++) {
        __syncthreads();   // Wt free to overwrite; also orders Ain producer->consumer on first chunk
        // stage W chunk [KT x D2] into smem, float4-coalesced
        const float4* src = (const float4*)(Wg + kc * KT * D2);
        float4* dst = (float4*)Wt;
        #pragma unroll
        for (int i = 0; i < (KT * D2 / 4) / NTHREADS; i++)
            dst[tid + i * NTHREADS] = src[tid + i * NTHREADS];
        __syncthreads();

        const float* Abase = Ain + (ty * 8) * D2 + kc * KT;
        #pragma unroll 2
        for (int k = 0; k < KT; k++) {
            float a[8];
            #pragma unroll
            for (int m = 0; m < 8; m++)
                a[m] = Abase[m * D2 + k];                 // warp-uniform -> smem broadcast
            float4 bb0 = *(const float4*)&Wt[k * D2 + tx * 8];
            float4 bb1 = *(const float4*)&Wt[k * D2 + tx * 8 + 4];
            float bb[8] = {bb0.x, bb0.y, bb0.z, bb0.w, bb1.x, bb1.y, bb1.z, bb1.w};
            #pragma unroll
            for (int m = 0; m < 8; m++)
                #pragma unroll
                for (int j = 0; j < 8; j++)
                    acc[m][j] = fmaf(a[m], bb[j], acc[m][j]);
        }
    }
}

__global__ __launch_bounds__(NTHREADS, 1)
void fused_mlp_kernel(const float* __restrict__ last,
                      const float* __restrict__ h,
                      const float* __restrict__ We,
                      const float* __restrict__ be,
                      const float* __restrict__ W1,
                      const float* __restrict__ b1,
                      const float* __restrict__ W2,
                      const float* __restrict__ b2,
                      const float* __restrict__ W3,
                      const float* __restrict__ b3,
                      float* __restrict__ out)
{
    extern __shared__ float sm[];
    float* A    = sm;                  // [MT][D2] layer-1 input (h | embed)
    float* A2   = A  + MT * D2;        // [MT][D2] layer-1 output
    float* Wt   = A2 + MT * D2;        // [KT][D2] W chunk
    float* sb1  = Wt + KT * D2;        // [D2]
    float* sb2  = sb1 + D2;            // [D2]
    float* sW3  = sb2 + D2;            // [2*D2] (row-major [256][2])
    float* sEmb = sW3 + 2 * D2;        // [HIDN]

    const int tid = threadIdx.x;
    const int r0  = blockIdx.x * MT;   // first global row of this tile
    const int g   = r0 / NPG;          // graph id (tile is entirely within one graph)

    // biases + W3 into smem
    if (tid < D2) {
        sb1[tid]      = b1[tid];
        sb2[tid]      = b2[tid];
        sW3[tid]      = W3[tid];
        sW3[tid + D2] = W3[tid + D2];
    }

    // per-graph node embed: embed[j] = be[j] + sum_k last[g,k] * We[k,j]
    if (tid < HIDN) {
        float acc = be[tid];
        const float* lrow = last + (size_t)g * INDIM;
        #pragma unroll 4
        for (int k = 0; k < INDIM; k++)
            acc = fmaf(lrow[k], We[k * HIDN + tid], acc);
        sEmb[tid] = acc;
    }
    __syncthreads();

    // Build stack tile A = [h_rows | embed broadcast]
    {
        const float4* h4 = (const float4*)(h + (size_t)r0 * HIDN);
        #pragma unroll
        for (int i = tid; i < MT * (HIDN / 4); i += NTHREADS) {
            int row = i >> 5;           // i / 32
            int c4  = i & 31;
            ((float4*)&A[row * D2])[c4] = h4[i];
        }
        const float4* e4 = (const float4*)sEmb;
        #pragma unroll
        for (int i = tid; i < MT * (HIDN / 4); i += NTHREADS) {
            int row = i >> 5;
            int c4  = i & 31;
            ((float4*)&A[row * D2 + HIDN])[c4] = e4[c4];
        }
    }

    const int tx = tid & 31;   // output-col block (tx*8 .. tx*8+7)
    const int ty = tid >> 5;   // output-row block (ty*8 .. ty*8+7) == warp id
    float acc[8][8];

    // ===== Layer 1: A -> tanh -> A2 =====
    do_layer(A, W1, Wt, sb1, tid, tx, ty, acc);
    #pragma unroll
    for (int m = 0; m < 8; m++) {
        float4 v0, v1;
        v0.x = tanhf(acc[m][0]); v0.y = tanhf(acc[m][1]);
        v0.z = tanhf(acc[m][2]); v0.w = tanhf(acc[m][3]);
        v1.x = tanhf(acc[m][4]); v1.y = tanhf(acc[m][5]);
        v1.z = tanhf(acc[m][6]); v1.w = tanhf(acc[m][7]);
        *(float4*)&A2[(ty * 8 + m) * D2 + tx * 8]     = v0;
        *(float4*)&A2[(ty * 8 + m) * D2 + tx * 8 + 4] = v1;
    }
    // (do_layer's leading __syncthreads orders A2 writes / Wt reuse for layer 2)

    // ===== Layer 2: A2 -> regs (no store) =====
    do_layer(A2, W2, Wt, sb2, tid, tx, ty, acc);

    // ===== Epilogue: tanh, multiply by W3 partials, warp-reduce across tx =====
    float e[8][2];
    #pragma unroll
    for (int m = 0; m < 8; m++) { e[m][0] = 0.f; e[m][1] = 0.f; }
    #pragma unroll
    for (int j = 0; j < 8; j++) {
        float w0 = sW3[(tx * 8 + j) * 2 + 0];
        float w1 = sW3[(tx * 8 + j) * 2 + 1];
        #pragma unroll
        for (int m = 0; m < 8; m++) {
            float o = tanhf(acc[m][j]);
            e[m][0] = fmaf(o, w0, e[m][0]);
            e[m][1] = fmaf(o, w1, e[m][1]);
        }
    }
    #pragma unroll
    for (int off = 16; off > 0; off >>= 1) {
        #pragma unroll
        for (int m = 0; m < 8; m++) {
            e[m][0] += __shfl_xor_sync(0xffffffffu, e[m][0], off);
            e[m][1] += __shfl_xor_sync(0xffffffffu, e[m][1], off);
        }
    }
    if (tx == 0) {
        float bb0 = b3[0], bb1 = b3[1];
        int p0 = (r0 & (NPG - 1)) + ty * 8;        // position within graph
        float* o = out + (size_t)g * (NPG * 2) + p0 * 2;
        #pragma unroll
        for (int m = 0; m < 8; m++) {
            o[m * 2 + 0] = e[m][0] + bb0;
            o[m * 2 + 1] = e[m][1] + bb1;
        }
    }
}

extern "C" void kernel_launch(void* const* d_in, const int* in_sizes, int n_in,
                              void* d_out, int out_size)
{
    const float* last = (const float*)d_in[0];
    const float* h    = (const float*)d_in[1];
    const float* We   = (const float*)d_in[2];
    const float* be   = (const float*)d_in[3];
    const float* W1   = (const float*)d_in[4];
    const float* b1   = (const float*)d_in[5];
    const float* W2   = (const float*)d_in[6];
    const float* b2   = (const float*)d_in[7];
    const float* W3   = (const float*)d_in[8];
    const float* b3   = (const float*)d_in[9];
    // d_in[10] = segment_ids (int64) and d_in[11] = max_nodes are structurally fixed; unused.
    float* out = (float*)d_out;

    cudaFuncSetAttribute(fused_mlp_kernel,
                         cudaFuncAttributeMaxDynamicSharedMemorySize, SM_BYTES);
    fused_mlp_kernel<<<NROWS / MT, NTHREADS, SM_BYTES>>>(
        last, h, We, be, W1, b1, W2, b2, W3, b3, out);
}

// round 4
// speedup vs baseline: 1.3657x; 1.3657x over previous
#include <cuda_runtime.h>
#include <cuda_bf16.h>
#include <stdint.h>
#include <math.h>

// ---------- problem constants ----------
#define NROWS    131072           // 512 graphs * 256 nodes
#define INDIM    128
#define HIDN     128
#define D2       256              // K and N of both big GEMMs
#define MTILE    64               // rows per CTA
#define NCTA     (NROWS / MTILE)  // 2048
#define NTHREADS 256              // 8 warps: wm in {0,1}, wn in {0..3}; warp tile 32x64

// ---------- smem layout (bytes) ----------
// A tiles: [16 kstep][64 row][16 k] bf16, hi and lo parts (32KB each)
#define SM_AHI   0
#define SM_ALO   32768
#define SM_EMB   65536            // 128 f32
#define SM_B1    66048            // 256 f32
#define SM_B2    67072            // 256 f32
#define SM_W3    68096            // 512 f32 ([256][2])
#define SM_RED   70144            // [4 wn][64 row][2] f32 = 2048B
#define SM_TOTAL 72192

// B fragments, fragment-major in global scratch:
// u32 index = ((((l*2+p)*16 + ks)*32 + lane)*64) + NT*2 + reg   (NT global 0..31)
__device__ uint32_t g_Bf[131072];   // 512KB

static __device__ __forceinline__ uint32_t pack_bf(__nv_bfloat16 a, __nv_bfloat16 b) {
    return ((uint32_t)__bfloat16_as_ushort(b) << 16) | (uint32_t)__bfloat16_as_ushort(a);
}
static __device__ __forceinline__ void split_bf(float v, __nv_bfloat16& hi, __nv_bfloat16& lo) {
    hi = __float2bfloat16(v);
    lo = __float2bfloat16(v - __bfloat162float(hi));
}

// ---------- prep: split W1/W2 into bf16 hi/lo fragments ----------
__global__ void prep_weights(const float* __restrict__ W1, const float* __restrict__ W2) {
    int i = blockIdx.x * blockDim.x + threadIdx.x;   // 0..131071
    int reg  = i & 1;
    int NT   = (i >> 1) & 31;
    int lane = (i >> 6) & 31;
    int ks   = (i >> 11) & 15;
    int p    = (i >> 15) & 1;
    int l    = i >> 16;
    const float* W = l ? W2 : W1;
    int k0 = ks * 16 + (lane & 3) * 2 + reg * 8;     // B frag: k rows tig*2(+1), +8 for reg1
    int n  = NT * 8 + (lane >> 2);                   // B frag col = groupID
    float v0 = W[k0 * 256 + n];
    float v1 = W[(k0 + 1) * 256 + n];
    __nv_bfloat16 h0, l0, h1, l1;
    split_bf(v0, h0, l0);
    split_bf(v1, h1, l1);
    g_Bf[i] = (p == 0) ? pack_bf(h0, h1) : pack_bf(l0, l1);
}

// ---------- mma.sync wrapper ----------
static __device__ __forceinline__ void mma_bf16(float* d, const uint32_t* a,
                                                uint32_t b0, uint32_t b1) {
    asm volatile(
        "mma.sync.aligned.m16n8k16.row.col.f32.bf16.bf16.f32 "
        "{%0,%1,%2,%3}, {%4,%5,%6,%7}, {%8,%9}, {%0,%1,%2,%3};"
        : "+f"(d[0]), "+f"(d[1]), "+f"(d[2]), "+f"(d[3])
        : "r"(a[0]), "r"(a[1]), "r"(a[2]), "r"(a[3]), "r"(b0), "r"(b1));
}

// A smem byte offset for (row r, k) with conflict-free xor swizzle.
// c' = (c + ((r&4)<<1)) & 15  where c = k&15; block = [kstep][64 rows][16 k]
static __device__ __forceinline__ uint32_t offA(int r, int k) {
    uint32_t c = (uint32_t)(k & 15);
    uint32_t cp = (c + (uint32_t)((r & 4) << 1)) & 15u;
    return ((uint32_t)(k >> 4) << 11) + ((uint32_t)r << 5) + (cp << 1);
}

// ---------- one GEMM layer: acc += A(smem,hi/lo) x B(frag-major global) ----------
static __device__ __forceinline__ void gemm_layer(const char* __restrict__ sm,
                                                  const uint32_t* __restrict__ gB,
                                                  int lane, int wm, int wn,
                                                  float (&acc)[2][8][4]) {
    const int g   = lane >> 2;
    const int tig = lane & 3;
    const int sw  = (g & 4) << 1;
    const int c0b = ((tig * 2 + sw) & 15) * 2;
    const int c2b = ((tig * 2 + 8 + sw) & 15) * 2;
    const int ro0 = g * 32;
    const int ro1 = (g + 8) * 32;

    #pragma unroll
    for (int mt = 0; mt < 2; mt++)
        #pragma unroll
        for (int nt = 0; nt < 8; nt++)
            #pragma unroll
            for (int c = 0; c < 4; c++)
                acc[mt][nt][c] = 0.f;

    #pragma unroll 2
    for (int ks = 0; ks < 16; ks++) {
        const uint32_t* bpH = gB + ((uint32_t)ks * 32 + lane) * 64 + wn * 16;
        const uint32_t* bpL = bpH + 32768;
        union { uint4 q[4]; uint32_t b[16]; } BH, BL;
        #pragma unroll
        for (int i = 0; i < 4; i++) {
            BH.q[i] = ((const uint4*)bpH)[i];
            BL.q[i] = ((const uint4*)bpL)[i];
        }

        uint32_t aH[2][4], aL[2][4];
        const char* Ab = sm + ((uint32_t)ks << 11);
        #pragma unroll
        for (int mt = 0; mt < 2; mt++) {
            int mb = (wm * 32 + mt * 16) * 32;
            aH[mt][0] = *(const uint32_t*)(Ab + SM_AHI + mb + ro0 + c0b);
            aH[mt][1] = *(const uint32_t*)(Ab + SM_AHI + mb + ro1 + c0b);
            aH[mt][2] = *(const uint32_t*)(Ab + SM_AHI + mb + ro0 + c2b);
            aH[mt][3] = *(const uint32_t*)(Ab + SM_AHI + mb + ro1 + c2b);
            aL[mt][0] = *(const uint32_t*)(Ab + SM_ALO + mb + ro0 + c0b);
            aL[mt][1] = *(const uint32_t*)(Ab + SM_ALO + mb + ro1 + c0b);
            aL[mt][2] = *(const uint32_t*)(Ab + SM_ALO + mb + ro0 + c2b);
            aL[mt][3] = *(const uint32_t*)(Ab + SM_ALO + mb + ro1 + c2b);
        }

        // pass-major: 16 independent MMAs between reuses of the same acc
        #pragma unroll
        for (int mt = 0; mt < 2; mt++)
            #pragma unroll
            for (int nt = 0; nt < 8; nt++)
                mma_bf16(acc[mt][nt], aH[mt], BH.b[nt * 2], BH.b[nt * 2 + 1]);
        #pragma unroll
        for (int mt = 0; mt < 2; mt++)
            #pragma unroll
            for (int nt = 0; nt < 8; nt++)
                mma_bf16(acc[mt][nt], aH[mt], BL.b[nt * 2], BL.b[nt * 2 + 1]);
        #pragma unroll
        for (int mt = 0; mt < 2; mt++)
            #pragma unroll
            for (int nt = 0; nt < 8; nt++)
                mma_bf16(acc[mt][nt], aL[mt], BH.b[nt * 2], BH.b[nt * 2 + 1]);
    }
}

// ---------- main fused kernel ----------
__global__ __launch_bounds__(NTHREADS, 1)
void fused_hmma_kernel(const float* __restrict__ last,
                       const float* __restrict__ h,
                       const float* __restrict__ We,
                       const float* __restrict__ be,
                       const float* __restrict__ b1,
                       const float* __restrict__ b2,
                       const float* __restrict__ W3,
                       const float* __restrict__ b3,
                       float* __restrict__ out) {
    extern __shared__ char sm[];
    const int tid  = threadIdx.x;
    const int lane = tid & 31;
    const int wid  = tid >> 5;
    const int wm   = wid >> 2;       // 0..1 (row half)
    const int wn   = wid & 3;        // 0..3 (64-col slice)
    const int r0   = blockIdx.x * MTILE;
    const int grp  = r0 >> 8;        // graph id (64 | 256)

    float* sEmb = (float*)(sm + SM_EMB);
    float* sB1  = (float*)(sm + SM_B1);
    float* sB2  = (float*)(sm + SM_B2);
    float* sW3  = (float*)(sm + SM_W3);
    float* sRed = (float*)(sm + SM_RED);

    sB1[tid] = b1[tid];
    sB2[tid] = b2[tid];
    sW3[tid]       = W3[tid];
    sW3[tid + 256] = W3[tid + 256];

    // per-graph embed (tid < 128)
    if (tid < HIDN) {
        float acc = be[tid];
        const float* lrow = last + (size_t)grp * INDIM;
        #pragma unroll 4
        for (int k = 0; k < INDIM; k++)
            acc = fmaf(lrow[k], We[k * HIDN + tid], acc);
        sEmb[tid] = acc;
    }

    // A tile, h half: 64 rows x 128 k (float4 strided)
    for (int idx = tid; idx < MTILE * 32; idx += NTHREADS) {
        int r = idx >> 5, kq = idx & 31, k = kq * 4;
        float4 v = *(const float4*)(h + (size_t)(r0 + r) * HIDN + k);
        __nv_bfloat16 h0, l0, h1, l1, h2, l2, h3, l3;
        split_bf(v.x, h0, l0); split_bf(v.y, h1, l1);
        split_bf(v.z, h2, l2); split_bf(v.w, h3, l3);
        uint32_t off = offA(r, k);                    // 8B-aligned (k%4==0)
        *(uint2*)(sm + SM_AHI + off) = make_uint2(pack_bf(h0, h1), pack_bf(h2, h3));
        *(uint2*)(sm + SM_ALO + off) = make_uint2(pack_bf(l0, l1), pack_bf(l2, l3));
    }
    __syncthreads();   // sEmb ready

    // A tile, embed half: k 128..255, broadcast across rows
    for (int idx = tid; idx < MTILE * 32; idx += NTHREADS) {
        int r = idx >> 5, kq = idx & 31, k = 128 + kq * 4;
        float4 v = *(const float4*)(sEmb + kq * 4);
        __nv_bfloat16 h0, l0, h1, l1, h2, l2, h3, l3;
        split_bf(v.x, h0, l0); split_bf(v.y, h1, l1);
        split_bf(v.z, h2, l2); split_bf(v.w, h3, l3);
        uint32_t off = offA(r, k);
        *(uint2*)(sm + SM_AHI + off) = make_uint2(pack_bf(h0, h1), pack_bf(h2, h3));
        *(uint2*)(sm + SM_ALO + off) = make_uint2(pack_bf(l0, l1), pack_bf(l2, l3));
    }
    __syncthreads();

    const int g   = lane >> 2;
    const int tig = lane & 3;
    float acc[2][8][4];

    // ===== Layer 1 =====
    gemm_layer(sm, g_Bf, lane, wm, wn, acc);
    __syncthreads();   // everyone done reading A

    // epilogue 1: tanh(+b1) -> re-split into A smem
    #pragma unroll
    for (int mt = 0; mt < 2; mt++) {
        int rA = wm * 32 + mt * 16 + g;
        int rB = rA + 8;
        #pragma unroll
        for (int nt = 0; nt < 8; nt++) {
            int c0 = wn * 64 + nt * 8 + tig * 2;
            float t0 = tanhf(acc[mt][nt][0] + sB1[c0]);
            float t1 = tanhf(acc[mt][nt][1] + sB1[c0 + 1]);
            float t2 = tanhf(acc[mt][nt][2] + sB1[c0]);
            float t3 = tanhf(acc[mt][nt][3] + sB1[c0 + 1]);
            __nv_bfloat16 h0, l0, h1, l1;
            split_bf(t0, h0, l0); split_bf(t1, h1, l1);
            uint32_t oA = offA(rA, c0);
            *(uint32_t*)(sm + SM_AHI + oA) = pack_bf(h0, h1);
            *(uint32_t*)(sm + SM_ALO + oA) = pack_bf(l0, l1);
            split_bf(t2, h0, l0); split_bf(t3, h1, l1);
            uint32_t oB = offA(rB, c0);
            *(uint32_t*)(sm + SM_AHI + oB) = pack_bf(h0, h1);
            *(uint32_t*)(sm + SM_ALO + oB) = pack_bf(l0, l1);
        }
    }
    __syncthreads();

    // ===== Layer 2 =====
    gemm_layer(sm, g_Bf + 65536, lane, wm, wn, acc);

    // epilogue 2: tanh(+b2), dot with W3, reduce
    float e[2][2][2];   // [mt][rowhalf][comp]
    #pragma unroll
    for (int mt = 0; mt < 2; mt++)
        #pragma unroll
        for (int hh = 0; hh < 2; hh++) { e[mt][hh][0] = 0.f; e[mt][hh][1] = 0.f; }

    #pragma unroll
    for (int mt = 0; mt < 2; mt++)
        #pragma unroll
        for (int nt = 0; nt < 8; nt++) {
            int c0 = wn * 64 + nt * 8 + tig * 2;
            float o0 = tanhf(acc[mt][nt][0] + sB2[c0]);
            float o1 = tanhf(acc[mt][nt][1] + sB2[c0 + 1]);
            float o2 = tanhf(acc[mt][nt][2] + sB2[c0]);
            float o3 = tanhf(acc[mt][nt][3] + sB2[c0 + 1]);
            float w00 = sW3[2 * c0],     w01 = sW3[2 * c0 + 1];
            float w10 = sW3[2 * c0 + 2], w11 = sW3[2 * c0 + 3];
            e[mt][0][0] = fmaf(o0, w00, fmaf(o1, w10, e[mt][0][0]));
            e[mt][0][1] = fmaf(o0, w01, fmaf(o1, w11, e[mt][0][1]));
            e[mt][1][0] = fmaf(o2, w00, fmaf(o3, w10, e[mt][1][0]));
            e[mt][1][1] = fmaf(o2, w01, fmaf(o3, w11, e[mt][1][1]));
        }
    // reduce across tig (lanes sharing the same rows)
    #pragma unroll
    for (int off = 1; off <= 2; off <<= 1)
        #pragma unroll
        for (int mt = 0; mt < 2; mt++)
            #pragma unroll
            for (int hh = 0; hh < 2; hh++) {
                e[mt][hh][0] += __shfl_xor_sync(0xffffffffu, e[mt][hh][0], off);
                e[mt][hh][1] += __shfl_xor_sync(0xffffffffu, e[mt][hh][1], off);
            }
    if (tig == 0) {
        #pragma unroll
        for (int mt = 0; mt < 2; mt++)
            #pragma unroll
            for (int hh = 0; hh < 2; hh++) {
                int row = wm * 32 + mt * 16 + g + hh * 8;
                sRed[wn * 128 + row * 2 + 0] = e[mt][hh][0];
                sRed[wn * 128 + row * 2 + 1] = e[mt][hh][1];
            }
    }
    __syncthreads();

    // final: sum 4 wn slices + b3, store
    if (tid < 128) {
        int row  = tid >> 1;
        int comp = tid & 1;
        float s = sRed[row * 2 + comp] + sRed[128 + row * 2 + comp]
                + sRed[256 + row * 2 + comp] + sRed[384 + row * 2 + comp]
                + b3[comp];
        int rg = r0 + row;
        out[(size_t)(rg >> 8) * 512 + (size_t)(rg & 255) * 2 + comp] = s;
    }
}

extern "C" void kernel_launch(void* const* d_in, const int* in_sizes, int n_in,
                              void* d_out, int out_size) {
    const float* last = (const float*)d_in[0];
    const float* h    = (const float*)d_in[1];
    const float* We   = (const float*)d_in[2];
    const float* be   = (const float*)d_in[3];
    const float* W1   = (const float*)d_in[4];
    const float* b1   = (const float*)d_in[5];
    const float* W2   = (const float*)d_in[6];
    const float* b2   = (const float*)d_in[7];
    const float* W3   = (const float*)d_in[8];
    const float* b3   = (const float*)d_in[9];
    float* out = (float*)d_out;

    prep_weights<<<512, 256>>>(W1, W2);

    cudaFuncSetAttribute(fused_hmma_kernel,
                         cudaFuncAttributeMaxDynamicSharedMemorySize, SM_TOTAL);
    fused_hmma_kernel<<<NCTA, NTHREADS, SM_TOTAL>>>(last, h, We, be, b1, b2, W3, b3, out);
}